// round 4
// baseline (speedup 1.0000x reference)
#include <cuda_runtime.h>
#include <math.h>
#include <float.h>

#define DD   64
#define TT   4096
#define NN   20000
#define MM   24096     // TT + NN
#define EE   100000
#define RR   50
#define TOKN 768

// ---------------- scratch (device globals; no allocation allowed) ----------------
__device__ __align__(16) float g_x[MM*DD];
__device__ __align__(16) float g_h[MM*DD];
__device__ __align__(16) float g_fx[MM*DD];
__device__ __align__(16) float g_aggr[MM*DD];
__device__ __align__(16) float g_W[RR*DD*DD];
__device__ __align__(16) float g_u1[RR*DD];
__device__ __align__(16) float g_u2[RR*DD];
__device__ int   g_rel[EE];
__device__ float g_mask[EE];
__device__ float g_p[MM];
__device__ float g_logit[EE];
__device__ float g_max;
__device__ float g_sum;
__device__ float g_kge;
__device__ float g_nt;

// ---------------- helpers ----------------
__device__ __forceinline__ void atomicMaxF(float* addr, float v) {
    int old = __float_as_int(*addr);
    while (__int_as_float(old) < v) {
        int prev = atomicCAS((int*)addr, old, __float_as_int(v));
        if (prev == old) break;
        old = prev;
    }
}

__device__ __forceinline__ void redAdd4(float* p, float4 v) {
    asm volatile("red.global.add.v4.f32 [%0], {%1, %2, %3, %4};"
                 :: "l"(p), "f"(v.x), "f"(v.y), "f"(v.z), "f"(v.w) : "memory");
}

__device__ __forceinline__ unsigned long long fmaf2(unsigned long long a,
                                                    unsigned long long b,
                                                    unsigned long long c) {
    unsigned long long d;
    asm("fma.rn.f32x2 %0, %1, %2, %3;" : "=l"(d) : "l"(a), "l"(b), "l"(c));
    return d;
}

__device__ __forceinline__ float2 u2f(unsigned long long v) {
    float2 r;
    asm("mov.b64 {%0, %1}, %2;" : "=f"(r.x), "=f"(r.y) : "l"(v));
    return r;
}

// ================= packed-f32x2 GEMM: C[m,n] = A[m,:K] @ B[:K,n] =================
// BM=128, BN=64, BK=32, 256 threads, per-thread 8 rows x 4 cols via 4x4 f32x2 accs.
#define LDA 132
#define LDB 136

template<int RELU, int HASADD, int ATOMIC, int ZEROADD>
__global__ void __launch_bounds__(256, 2)
gemm_f2(const float* __restrict__ A, const float* __restrict__ B,
        const float* __restrict__ bias, float* __restrict__ addsrc,
        float* __restrict__ C, int Mrows, int N, int K, int kPerZ)
{
    __shared__ float shA[32*LDA];
    __shared__ float shB[32*LDB];
    int tid  = threadIdx.x;
    int row0 = blockIdx.y * 128;
    int col0 = blockIdx.x * 64;
    int ctid = tid & 15;
    int rtid = tid >> 4;
    int c0 = ctid * 4;
    int r0 = rtid * 8;

    unsigned long long acc[4][4];
    #pragma unroll
    for (int i = 0; i < 4; i++)
        #pragma unroll
        for (int j = 0; j < 4; j++) acc[i][j] = 0ULL;

    int kb = blockIdx.z * kPerZ;
    for (int kc = kb; kc < kb + kPerZ; kc += 32) {
        #pragma unroll
        for (int i = 0; i < 4; i++) {
            int lin = tid + i * 256;
            int row = lin & 127;
            int kq  = lin >> 7;
            float4 v = make_float4(0.f, 0.f, 0.f, 0.f);
            if (row0 + row < Mrows)
                v = *(const float4*)&A[(long)(row0 + row) * K + kc + kq * 4];
            shA[(kq*4 + 0)*LDA + row] = v.x;
            shA[(kq*4 + 1)*LDA + row] = v.y;
            shA[(kq*4 + 2)*LDA + row] = v.z;
            shA[(kq*4 + 3)*LDA + row] = v.w;
        }
        #pragma unroll
        for (int i = 0; i < 2; i++) {
            int lin = tid + i * 256;
            int c4 = lin & 15;
            int k  = lin >> 4;
            float4 v = *(const float4*)&B[(long)(kc + k) * N + col0 + c4 * 4];
            *(float4*)&shB[k*LDB + c4*8]     = make_float4(v.x, v.x, v.y, v.y);
            *(float4*)&shB[k*LDB + c4*8 + 4] = make_float4(v.z, v.z, v.w, v.w);
        }
        __syncthreads();

        #pragma unroll
        for (int k = 0; k < 32; k++) {
            ulonglong2 a01 = *(const ulonglong2*)&shA[k*LDA + r0];
            ulonglong2 a23 = *(const ulonglong2*)&shA[k*LDA + r0 + 4];
            ulonglong2 b01 = *(const ulonglong2*)&shB[k*LDB + c0*2];
            ulonglong2 b23 = *(const ulonglong2*)&shB[k*LDB + c0*2 + 4];
            acc[0][0] = fmaf2(a01.x, b01.x, acc[0][0]);
            acc[0][1] = fmaf2(a01.x, b01.y, acc[0][1]);
            acc[0][2] = fmaf2(a01.x, b23.x, acc[0][2]);
            acc[0][3] = fmaf2(a01.x, b23.y, acc[0][3]);
            acc[1][0] = fmaf2(a01.y, b01.x, acc[1][0]);
            acc[1][1] = fmaf2(a01.y, b01.y, acc[1][1]);
            acc[1][2] = fmaf2(a01.y, b23.x, acc[1][2]);
            acc[1][3] = fmaf2(a01.y, b23.y, acc[1][3]);
            acc[2][0] = fmaf2(a23.x, b01.x, acc[2][0]);
            acc[2][1] = fmaf2(a23.x, b01.y, acc[2][1]);
            acc[2][2] = fmaf2(a23.x, b23.x, acc[2][2]);
            acc[2][3] = fmaf2(a23.x, b23.y, acc[2][3]);
            acc[3][0] = fmaf2(a23.y, b01.x, acc[3][0]);
            acc[3][1] = fmaf2(a23.y, b01.y, acc[3][1]);
            acc[3][2] = fmaf2(a23.y, b23.x, acc[3][2]);
            acc[3][3] = fmaf2(a23.y, b23.y, acc[3][3]);
        }
        __syncthreads();
    }

    float4 bv = *(const float4*)&bias[col0 + c0];
    bool addbias = !ATOMIC || (blockIdx.z == 0);

    #pragma unroll
    for (int rp = 0; rp < 4; rp++) {
        float2 f0 = u2f(acc[rp][0]);
        float2 f1 = u2f(acc[rp][1]);
        float2 f2 = u2f(acc[rp][2]);
        float2 f3 = u2f(acc[rp][3]);
        float4 vlo = make_float4(f0.x, f1.x, f2.x, f3.x);
        float4 vhi = make_float4(f0.y, f1.y, f2.y, f3.y);
        #pragma unroll
        for (int half = 0; half < 2; half++) {
            int row = row0 + r0 + rp*2 + half;
            if (row >= Mrows) continue;
            float4 v = half ? vhi : vlo;
            if (addbias) { v.x += bv.x; v.y += bv.y; v.z += bv.z; v.w += bv.w; }
            if (HASADD) {
                float4 ad = *(float4*)&addsrc[(long)row * N + col0 + c0];
                v.x += ad.x; v.y += ad.y; v.z += ad.z; v.w += ad.w;
                if (ZEROADD)
                    *(float4*)&addsrc[(long)row * N + col0 + c0] =
                        make_float4(0.f, 0.f, 0.f, 0.f);
            }
            if (RELU) {
                v.x = fmaxf(v.x, 0.f); v.y = fmaxf(v.y, 0.f);
                v.z = fmaxf(v.z, 0.f); v.w = fmaxf(v.w, 0.f);
            }
            if (ATOMIC) {
                redAdd4(&C[(long)row * N + col0 + c0], v);
            } else {
                *(float4*)&C[(long)row * N + col0 + c0] = v;
            }
        }
    }
}

// ---------------- init: zero aggr + tok region of x, gather kg nodes, reset scalars ----
__global__ void k_init(const int* __restrict__ node_ids, const float* __restrict__ kg_emb)
{
    int idx = blockIdx.x * blockDim.x + threadIdx.x;   // float4 units
    float4 z = make_float4(0.f, 0.f, 0.f, 0.f);
    if (idx < MM*16) ((float4*)g_aggr)[idx] = z;
    if (idx < TT*16) ((float4*)g_x)[idx] = z;
    if (idx < NN*16) {
        int n = idx >> 4, q = idx & 15;
        ((float4*)g_x)[(long)(TT + n)*16 + q] =
            ((const float4*)kg_emb)[(long)node_ids[n]*16 + q];
    }
    if (idx == 0) { g_kge = 0.f; g_nt = 0.f; }
}

// ---------------- edge prep: relation id + mask; u tables (after W gemm) ----------------
// edge_attr rows are 50 floats = 200 bytes: 8-byte aligned for every e, NOT 16.
// Use float2 loads only.
#define EB ((EE + 255)/256)
__global__ void k_edgeprep(const float* __restrict__ ea,
                           const float* __restrict__ att1_w,
                           const float* __restrict__ att2_w)
{
    int b = blockIdx.x;
    if (b < EB) {
        int e = b * 256 + threadIdx.x;
        if (e >= EE) return;
        const float2* row = (const float2*)(ea + (long)e * RR);
        float acc = 0.f;
        #pragma unroll
        for (int i = 0; i < 25; i++) {
            float2 v = row[i];
            acc += v.x * (2*i) + v.y * (2*i + 1);
        }
        const float* rowf = (const float*)row;
        float l47 = rowf[47], l48 = rowf[48], l49 = rowf[49];
        g_rel[e] = (int)(acc + 0.5f);
        g_mask[e] = (l47 + l48 + l49 == 0.f) ? 1.f : 0.f;
    } else {
        int idx = (b - EB) * 256 + threadIdx.x;
        if (idx >= RR*DD) return;
        int rel = idx >> 6, d = idx & 63;
        const float4* wrow = (const float4*)(g_W + (long)rel*4096 + d*64);
        const float4* w1 = (const float4*)(att1_w + 64);
        const float4* w2 = (const float4*)(att2_w + 64);
        float a1 = 0.f, a2 = 0.f;
        #pragma unroll
        for (int o = 0; o < 16; o++) {
            float4 w = wrow[o];
            float4 v1 = w1[o], v2 = w2[o];
            a1 += w.x*v1.x + w.y*v1.y + w.z*v1.z + w.w*v1.w;
            a2 += w.x*v2.x + w.y*v2.y + w.z*v2.z + w.w*v2.w;
        }
        g_u1[idx] = a1; g_u2[idx] = a2;
    }
}

// ---------------- per-node dst-side attention term p[n] = att_b + x[n].w1; reset scalars --
__global__ void k_p(const float* __restrict__ x, const float* __restrict__ att_w,
                    const float* __restrict__ att_b)
{
    int n = blockIdx.x * blockDim.x + threadIdx.x;
    if (n == 0) { g_max = -FLT_MAX; g_sum = 0.f; }
    if (n >= MM) return;
    float acc = att_b[0];
    const float4* xr = (const float4*)(x + (long)n * DD);
    const float4* wr = (const float4*)att_w;
    #pragma unroll
    for (int k = 0; k < 16; k++) {
        float4 a = xr[k], w = wr[k];
        acc += a.x*w.x + a.y*w.y + a.z*w.z + a.w*w.w;
    }
    g_p[n] = acc;
}

// ---------------- edge logits + running max ----------------
__global__ void k_logit(const float* __restrict__ x, const float* __restrict__ u,
                        const int* __restrict__ src, const int* __restrict__ dst)
{
    __shared__ float sm[256];
    int e = blockIdx.x * 256 + threadIdx.x;
    float l = -FLT_MAX;
    if (e < EE) {
        int s = src[e];
        float acc = g_p[dst[e]];
        const float4* xr = (const float4*)(x + (long)s * DD);
        const float4* ur = (const float4*)(u + g_rel[e] * DD);
        #pragma unroll
        for (int k = 0; k < 16; k++) {
            float4 a = xr[k], w = ur[k];
            acc += a.x*w.x + a.y*w.y + a.z*w.z + a.w*w.w;
        }
        g_logit[e] = acc;
        l = acc;
    }
    sm[threadIdx.x] = l; __syncthreads();
    for (int s = 128; s > 0; s >>= 1) {
        if (threadIdx.x < s) sm[threadIdx.x] = fmaxf(sm[threadIdx.x], sm[threadIdx.x + s]);
        __syncthreads();
    }
    if (threadIdx.x == 0) atomicMaxF(&g_max, sm[0]);
}

// ---------------- exp(logit - max), running sum ----------------
__global__ void k_expsum()
{
    __shared__ float sm[256];
    int e = blockIdx.x * 256 + threadIdx.x;
    float v = 0.f;
    if (e < EE) {
        v = __expf(g_logit[e] - g_max);
        g_logit[e] = v;
    }
    sm[threadIdx.x] = v; __syncthreads();
    for (int s = 128; s > 0; s >>= 1) {
        if (threadIdx.x < s) sm[threadIdx.x] += sm[threadIdx.x + s];
        __syncthreads();
    }
    if (threadIdx.x == 0) atomicAdd(&g_sum, sm[0]);
}

// ---------------- message scatter: aggr[dst] += x[src] * alpha (vector atomics) -------
__global__ void k_scatter(const float* __restrict__ x, const int* __restrict__ src,
                          const int* __restrict__ dst)
{
    int idx = blockIdx.x * 256 + threadIdx.x;   // over EE*16 float4 units
    if (idx >= EE * 16) return;
    int e = idx >> 4, q = idx & 15;
    float a = g_logit[e] / g_sum;
    float4 v = *(const float4*)&x[(long)src[e]*DD + q*4];
    v.x *= a; v.y *= a; v.z *= a; v.w *= a;
    redAdd4(&g_aggr[(long)dst[e]*DD + q*4], v);
}

// ---------------- fused losses: kge (blocks < KB) + nt (rest) ----------------
#define KB 512
__global__ void k_loss(const int* __restrict__ src, const int* __restrict__ dst,
                       const float* __restrict__ rel_emb,
                       const int* __restrict__ labels,
                       const float* __restrict__ w_nt, const float* __restrict__ b_nt)
{
    __shared__ float sm[256];
    if (blockIdx.x < KB) {
        float acc = 0.f;
        for (long idx = (long)blockIdx.x * 256 + threadIdx.x; idx < (long)EE * 16;
             idx += (long)KB * 256) {
            int e = (int)(idx >> 4), q = (int)(idx & 15);
            if (g_mask[e] != 0.f) {
                float4 a = *(const float4*)&g_fx[(long)src[e]*DD + q*4];
                float4 b = *(const float4*)&g_fx[(long)dst[e]*DD + q*4];
                float4 r = *(const float4*)&rel_emb[g_rel[e]*DD + q*4];
                float dx = a.x + r.x - b.x;
                float dy = a.y + r.y - b.y;
                float dz = a.z + r.z - b.z;
                float dw = a.w + r.w - b.w;
                acc += dx*dx + dy*dy + dz*dz + dw*dw;
            }
        }
        sm[threadIdx.x] = acc; __syncthreads();
        for (int s = 128; s > 0; s >>= 1) {
            if (threadIdx.x < s) sm[threadIdx.x] += sm[threadIdx.x + s];
            __syncthreads();
        }
        if (threadIdx.x == 0) atomicAdd(&g_kge, sm[0]);
    } else {
        int n = (blockIdx.x - KB) * 256 + threadIdx.x;
        float loss = 0.f;
        if (n < MM) {
            const float* xr = g_fx + (long)n * DD;
            float z0 = b_nt[0], z1 = b_nt[1], z2 = b_nt[2];
            #pragma unroll 16
            for (int k = 0; k < DD; k++) {
                float v = xr[k];
                z0 += v * w_nt[k*3 + 0];
                z1 += v * w_nt[k*3 + 1];
                z2 += v * w_nt[k*3 + 2];
            }
            float mx  = fmaxf(z0, fmaxf(z1, z2));
            float lse = mx + logf(expf(z0 - mx) + expf(z1 - mx) + expf(z2 - mx));
            int lab = labels[n];
            float zl = (lab == 0) ? z0 : ((lab == 1) ? z1 : z2);
            loss = lse - zl;
        }
        sm[threadIdx.x] = loss; __syncthreads();
        for (int s = 128; s > 0; s >>= 1) {
            if (threadIdx.x < s) sm[threadIdx.x] += sm[threadIdx.x + s];
            __syncthreads();
        }
        if (threadIdx.x == 0) atomicAdd(&g_nt, sm[0]);
    }
}

// ---------------- write loss scalars ----------------
__global__ void k_finalize(float* __restrict__ out, long off)
{
    out[off]     = g_kge / (float)((long)EE * DD);
    out[off + 1] = g_nt / (float)MM;
}

// =====================================================================================
extern "C" void kernel_launch(void* const* d_in, const int* in_sizes, int n_in,
                              void* d_out, int out_size)
{
    const int*   node_ids   = (const int*)  d_in[0];
    const int*   edge_index = (const int*)  d_in[1];
    const float* edge_attr  = (const float*)d_in[2];
    const float* tokemb     = (const float*)d_in[3];
    const int*   labels     = (const int*)  d_in[4];
    const float* kg_emb     = (const float*)d_in[5];
    const float* rel_emb    = (const float*)d_in[6];
    const float* w_e2       = (const float*)d_in[7];
    const float* b_e2       = (const float*)d_in[8];
    const float* att1_w     = (const float*)d_in[9];
    const float* att1_b     = (const float*)d_in[10];
    const float* root1      = (const float*)d_in[11];
    const float* bias1      = (const float*)d_in[12];
    const float* att2_w     = (const float*)d_in[13];
    const float* att2_b     = (const float*)d_in[14];
    const float* root2      = (const float*)d_in[15];
    const float* bias2      = (const float*)d_in[16];
    const float* w_lin1     = (const float*)d_in[17];
    const float* b_lin1     = (const float*)d_in[18];
    const float* w_lin2     = (const float*)d_in[19];
    const float* b_lin2     = (const float*)d_in[20];
    const float* w_nt       = (const float*)d_in[21];
    const float* b_nt       = (const float*)d_in[22];
    float* out = (float*)d_out;

    const int* src = edge_index;        // edge_index[0, :]
    const int* dst = edge_index + EE;   // edge_index[1, :]

    void *px_, *ph_, *pfx_, *paggr_, *pW_, *pu1_, *pu2_;
    cudaGetSymbolAddress(&px_,    g_x);
    cudaGetSymbolAddress(&ph_,    g_h);
    cudaGetSymbolAddress(&pfx_,   g_fx);
    cudaGetSymbolAddress(&paggr_, g_aggr);
    cudaGetSymbolAddress(&pu1_,   g_u1);
    cudaGetSymbolAddress(&pu2_,   g_u2);
    cudaGetSymbolAddress(&pW_,    g_W);
    float* px    = (float*)px_;
    float* ph    = (float*)ph_;
    float* pfx   = (float*)pfx_;
    float* paggr = (float*)paggr_;
    float* pu1   = (float*)pu1_;
    float* pu2   = (float*)pu2_;
    float* pW    = (float*)pW_;

    // ---- init scratch (zero aggr + tok region, gather kg nodes, reset scalars) ----
    k_init<<<(MM*16 + 255)/256, 256>>>(node_ids, kg_emb);

    // ---- tok = token_embeddings @ w_lin1 + b_lin1 (split-K over z, atomic) ----
    {
        dim3 grid(1, (TT + 127)/128, 8);
        gemm_f2<0,0,1,0><<<grid, 256>>>(tokemb, w_lin1, b_lin1, nullptr, px, TT, DD, TOKN, 96);
    }

    // ---- W[r] = relu(rel_emb @ w_e2 + b_e2) as GEMM [50,64]x[64,4096] ----
    {
        dim3 grid(4096/64, 1, 1);
        gemm_f2<1,0,0,0><<<grid, 256>>>(rel_emb, w_e2, b_e2, nullptr, pW, RR, 4096, DD, DD);
    }
    k_edgeprep<<<EB + (RR*DD + 255)/256, 256>>>(edge_attr, att1_w, att2_w);

    // ---- layer 1: x -> h (relu); gemm re-zeroes aggr for layer 2 ----
    k_p<<<(MM + 255)/256, 256>>>(px, att1_w, att1_b);
    k_logit<<<(EE + 255)/256, 256>>>(px, pu1, src, dst);
    k_expsum<<<(EE + 255)/256, 256>>>();
    k_scatter<<<(EE*16 + 255)/256, 256>>>(px, src, dst);
    {
        dim3 grid(1, (MM + 127)/128, 1);
        gemm_f2<1,1,0,1><<<grid, 256>>>(px, root1, bias1, paggr, ph, MM, DD, DD, DD);
    }

    // ---- layer 2: h -> final_x ----
    k_p<<<(MM + 255)/256, 256>>>(ph, att2_w, att2_b);
    k_logit<<<(EE + 255)/256, 256>>>(ph, pu2, src, dst);
    k_expsum<<<(EE + 255)/256, 256>>>();
    k_scatter<<<(EE*16 + 255)/256, 256>>>(ph, src, dst);
    {
        dim3 grid(1, (MM + 127)/128, 1);
        gemm_f2<0,1,0,0><<<grid, 256>>>(ph, root2, bias2, paggr, pfx, MM, DD, DD, DD);
    }

    // ---- losses (fused) ----
    k_loss<<<KB + (MM + 255)/256, 256>>>(src, dst, rel_emb, labels, w_nt, b_nt);

    // ---- final outputs: final_x @ w_lin2 + b_lin2 ----
    {
        dim3 grid(TOKN/64, (MM + 127)/128, 1);
        gemm_f2<0,0,0,0><<<grid, 256>>>(pfx, w_lin2, b_lin2, nullptr, out, MM, TOKN, DD, DD);
    }

    // ---- loss scalars at the tail of d_out ----
    k_finalize<<<1, 1>>>(out, (long)out_size - 2);
}

// round 5
// speedup vs baseline: 1.3987x; 1.3987x over previous
#include <cuda_runtime.h>
#include <math.h>
#include <float.h>

#define DD   64
#define TT   4096
#define NN   20000
#define MM   24096     // TT + NN
#define EE   100000
#define RR   50
#define TOKN 768

// ---------------- scratch (device globals; no allocation allowed) ----------------
__device__ __align__(16) float g_x[MM*DD];
__device__ __align__(16) float g_h[MM*DD];
__device__ __align__(16) float g_fx[MM*DD];
__device__ __align__(16) float g_aggr[MM*DD];
__device__ __align__(16) float g_W[RR*DD*DD];
__device__ __align__(16) float g_u1[RR*DD];
__device__ __align__(16) float g_u2[RR*DD];
__device__ int   g_rel[EE];
__device__ float g_mask[EE];
__device__ float g_p[MM];
__device__ float g_logit[EE];
__device__ float g_max;
__device__ float g_sum;
__device__ float g_kge;
__device__ float g_nt;

// ---------------- helpers ----------------
__device__ __forceinline__ void atomicMaxF(float* addr, float v) {
    int old = __float_as_int(*addr);
    while (__int_as_float(old) < v) {
        int prev = atomicCAS((int*)addr, old, __float_as_int(v));
        if (prev == old) break;
        old = prev;
    }
}

__device__ __forceinline__ unsigned long long fmaf2(unsigned long long a,
                                                    unsigned long long b,
                                                    unsigned long long c) {
    unsigned long long d;
    asm("fma.rn.f32x2 %0, %1, %2, %3;" : "=l"(d) : "l"(a), "l"(b), "l"(c));
    return d;
}

__device__ __forceinline__ float2 u2f(unsigned long long v) {
    float2 r;
    asm("mov.b64 {%0, %1}, %2;" : "=f"(r.x), "=f"(r.y) : "l"(v));
    return r;
}

// ================= packed-f32x2 GEMM: C[m,n] = A[m,:K] @ B[:K,n] =================
// BM=128, BN=64, BK=32, 256 threads, per-thread 8 rows x 4 cols via 4x4 f32x2 accs.
#define LDA 132
#define LDB 136

template<int RELU, int HASADD, int ATOMIC, int ZEROADD>
__global__ void __launch_bounds__(256, 2)
gemm_f2(const float* __restrict__ A, const float* __restrict__ B,
        const float* __restrict__ bias, float* __restrict__ addsrc,
        float* __restrict__ C, int Mrows, int N, int K, int kPerZ)
{
    __shared__ float shA[32*LDA];
    __shared__ float shB[32*LDB];
    int tid  = threadIdx.x;
    int row0 = blockIdx.y * 128;
    int col0 = blockIdx.x * 64;
    int ctid = tid & 15;
    int rtid = tid >> 4;
    int c0 = ctid * 4;
    int r0 = rtid * 8;

    unsigned long long acc[4][4];
    #pragma unroll
    for (int i = 0; i < 4; i++)
        #pragma unroll
        for (int j = 0; j < 4; j++) acc[i][j] = 0ULL;

    int kb = blockIdx.z * kPerZ;
    for (int kc = kb; kc < kb + kPerZ; kc += 32) {
        #pragma unroll
        for (int i = 0; i < 4; i++) {
            int lin = tid + i * 256;
            int row = lin & 127;
            int kq  = lin >> 7;
            float4 v = make_float4(0.f, 0.f, 0.f, 0.f);
            if (row0 + row < Mrows)
                v = *(const float4*)&A[(long)(row0 + row) * K + kc + kq * 4];
            shA[(kq*4 + 0)*LDA + row] = v.x;
            shA[(kq*4 + 1)*LDA + row] = v.y;
            shA[(kq*4 + 2)*LDA + row] = v.z;
            shA[(kq*4 + 3)*LDA + row] = v.w;
        }
        #pragma unroll
        for (int i = 0; i < 2; i++) {
            int lin = tid + i * 256;
            int c4 = lin & 15;
            int k  = lin >> 4;
            float4 v = *(const float4*)&B[(long)(kc + k) * N + col0 + c4 * 4];
            *(float4*)&shB[k*LDB + c4*8]     = make_float4(v.x, v.x, v.y, v.y);
            *(float4*)&shB[k*LDB + c4*8 + 4] = make_float4(v.z, v.z, v.w, v.w);
        }
        __syncthreads();

        #pragma unroll
        for (int k = 0; k < 32; k++) {
            ulonglong2 a01 = *(const ulonglong2*)&shA[k*LDA + r0];
            ulonglong2 a23 = *(const ulonglong2*)&shA[k*LDA + r0 + 4];
            ulonglong2 b01 = *(const ulonglong2*)&shB[k*LDB + c0*2];
            ulonglong2 b23 = *(const ulonglong2*)&shB[k*LDB + c0*2 + 4];
            acc[0][0] = fmaf2(a01.x, b01.x, acc[0][0]);
            acc[0][1] = fmaf2(a01.x, b01.y, acc[0][1]);
            acc[0][2] = fmaf2(a01.x, b23.x, acc[0][2]);
            acc[0][3] = fmaf2(a01.x, b23.y, acc[0][3]);
            acc[1][0] = fmaf2(a01.y, b01.x, acc[1][0]);
            acc[1][1] = fmaf2(a01.y, b01.y, acc[1][1]);
            acc[1][2] = fmaf2(a01.y, b23.x, acc[1][2]);
            acc[1][3] = fmaf2(a01.y, b23.y, acc[1][3]);
            acc[2][0] = fmaf2(a23.x, b01.x, acc[2][0]);
            acc[2][1] = fmaf2(a23.x, b01.y, acc[2][1]);
            acc[2][2] = fmaf2(a23.x, b23.x, acc[2][2]);
            acc[2][3] = fmaf2(a23.x, b23.y, acc[2][3]);
            acc[3][0] = fmaf2(a23.y, b01.x, acc[3][0]);
            acc[3][1] = fmaf2(a23.y, b01.y, acc[3][1]);
            acc[3][2] = fmaf2(a23.y, b23.x, acc[3][2]);
            acc[3][3] = fmaf2(a23.y, b23.y, acc[3][3]);
        }
        __syncthreads();
    }

    float4 bv = *(const float4*)&bias[col0 + c0];
    bool addbias = !ATOMIC || (blockIdx.z == 0);

    #pragma unroll
    for (int rp = 0; rp < 4; rp++) {
        float2 f0 = u2f(acc[rp][0]);
        float2 f1 = u2f(acc[rp][1]);
        float2 f2 = u2f(acc[rp][2]);
        float2 f3 = u2f(acc[rp][3]);
        float4 vlo = make_float4(f0.x, f1.x, f2.x, f3.x);
        float4 vhi = make_float4(f0.y, f1.y, f2.y, f3.y);
        #pragma unroll
        for (int half = 0; half < 2; half++) {
            int row = row0 + r0 + rp*2 + half;
            if (row >= Mrows) continue;
            float4 v = half ? vhi : vlo;
            if (addbias) { v.x += bv.x; v.y += bv.y; v.z += bv.z; v.w += bv.w; }
            if (HASADD) {
                float4 ad = *(float4*)&addsrc[(long)row * N + col0 + c0];
                v.x += ad.x; v.y += ad.y; v.z += ad.z; v.w += ad.w;
                if (ZEROADD)
                    *(float4*)&addsrc[(long)row * N + col0 + c0] =
                        make_float4(0.f, 0.f, 0.f, 0.f);
            }
            if (RELU) {
                v.x = fmaxf(v.x, 0.f); v.y = fmaxf(v.y, 0.f);
                v.z = fmaxf(v.z, 0.f); v.w = fmaxf(v.w, 0.f);
            }
            if (ATOMIC) {
                float* cp = &C[(long)row * N + col0 + c0];
                atomicAdd(cp + 0, v.x); atomicAdd(cp + 1, v.y);
                atomicAdd(cp + 2, v.z); atomicAdd(cp + 3, v.w);
            } else {
                *(float4*)&C[(long)row * N + col0 + c0] = v;
            }
        }
    }
}

// ---------------- init: zero aggr + tok region of x, gather kg nodes, reset scalars ----
__global__ void k_init(const int* __restrict__ node_ids, const float* __restrict__ kg_emb)
{
    int idx = blockIdx.x * blockDim.x + threadIdx.x;   // float4 units
    float4 z = make_float4(0.f, 0.f, 0.f, 0.f);
    if (idx < MM*16) ((float4*)g_aggr)[idx] = z;
    if (idx < TT*16) ((float4*)g_x)[idx] = z;
    if (idx < NN*16) {
        int n = idx >> 4, q = idx & 15;
        ((float4*)g_x)[(long)(TT + n)*16 + q] =
            ((const float4*)kg_emb)[(long)node_ids[n]*16 + q];
    }
    if (idx == 0) { g_kge = 0.f; g_nt = 0.f; }
}

// ---------------- edge prep: relation id + mask (smem-staged, coalesced); u tables ----
#define EPB 128                       // edges per block
#define EB  ((EE + EPB - 1) / EPB)    // 782 blocks for the edge part
__global__ void k_edgeprep(const float* __restrict__ ea,
                           const float* __restrict__ att1_w,
                           const float* __restrict__ att2_w)
{
    int b = blockIdx.x;
    if (b < EB) {
        __shared__ float sm[EPB * RR];
        int e0 = b * EPB;
        int cnt = min(EPB, EE - e0);
        int total = cnt * RR;
        const float* base = ea + (long)e0 * RR;
        for (int i = threadIdx.x; i < total; i += 256) sm[i] = base[i];
        __syncthreads();
        int el = threadIdx.x;
        if (el < cnt) {
            const float* row = sm + el * RR;
            float acc = 0.f;
            #pragma unroll
            for (int r = 1; r < RR; r++) acc += row[r] * (float)r;
            g_rel[e0 + el] = (int)(acc + 0.5f);
            g_mask[e0 + el] = (row[47] + row[48] + row[49] == 0.f) ? 1.f : 0.f;
        }
    } else {
        int idx = (b - EB) * 256 + threadIdx.x;
        if (idx >= RR*DD) return;
        int rel = idx >> 6, d = idx & 63;
        const float4* wrow = (const float4*)(g_W + (long)rel*4096 + d*64);
        const float4* w1 = (const float4*)(att1_w + 64);
        const float4* w2 = (const float4*)(att2_w + 64);
        float a1 = 0.f, a2 = 0.f;
        #pragma unroll
        for (int o = 0; o < 16; o++) {
            float4 w = wrow[o];
            float4 v1 = w1[o], v2 = w2[o];
            a1 += w.x*v1.x + w.y*v1.y + w.z*v1.z + w.w*v1.w;
            a2 += w.x*v2.x + w.y*v2.y + w.z*v2.z + w.w*v2.w;
        }
        g_u1[idx] = a1; g_u2[idx] = a2;
    }
}

// ---------------- per-node dst-side attention term p[n] = att_b + x[n].w1; reset scalars --
__global__ void k_p(const float* __restrict__ x, const float* __restrict__ att_w,
                    const float* __restrict__ att_b)
{
    int n = blockIdx.x * blockDim.x + threadIdx.x;
    if (n == 0) { g_max = -FLT_MAX; g_sum = 0.f; }
    if (n >= MM) return;
    float acc = att_b[0];
    const float4* xr = (const float4*)(x + (long)n * DD);
    const float4* wr = (const float4*)att_w;
    #pragma unroll
    for (int k = 0; k < 16; k++) {
        float4 a = xr[k], w = wr[k];
        acc += a.x*w.x + a.y*w.y + a.z*w.z + a.w*w.w;
    }
    g_p[n] = acc;
}

// ---------------- edge logits + running max ----------------
__global__ void k_logit(const float* __restrict__ x, const float* __restrict__ u,
                        const int* __restrict__ src, const int* __restrict__ dst)
{
    __shared__ float sm[256];
    int e = blockIdx.x * 256 + threadIdx.x;
    float l = -FLT_MAX;
    if (e < EE) {
        int s = src[e];
        float acc = g_p[dst[e]];
        const float4* xr = (const float4*)(x + (long)s * DD);
        const float4* ur = (const float4*)(u + g_rel[e] * DD);
        #pragma unroll
        for (int k = 0; k < 16; k++) {
            float4 a = xr[k], w = ur[k];
            acc += a.x*w.x + a.y*w.y + a.z*w.z + a.w*w.w;
        }
        g_logit[e] = acc;
        l = acc;
    }
    sm[threadIdx.x] = l; __syncthreads();
    for (int s = 128; s > 0; s >>= 1) {
        if (threadIdx.x < s) sm[threadIdx.x] = fmaxf(sm[threadIdx.x], sm[threadIdx.x + s]);
        __syncthreads();
    }
    if (threadIdx.x == 0) atomicMaxF(&g_max, sm[0]);
}

// ---------------- exp(logit - max), running sum ----------------
__global__ void k_expsum()
{
    __shared__ float sm[256];
    int e = blockIdx.x * 256 + threadIdx.x;
    float v = 0.f;
    if (e < EE) {
        v = __expf(g_logit[e] - g_max);
        g_logit[e] = v;
    }
    sm[threadIdx.x] = v; __syncthreads();
    for (int s = 128; s > 0; s >>= 1) {
        if (threadIdx.x < s) sm[threadIdx.x] += sm[threadIdx.x + s];
        __syncthreads();
    }
    if (threadIdx.x == 0) atomicAdd(&g_sum, sm[0]);
}

// ---------------- message scatter: aggr[dst] += x[src] * alpha (scalar atomics) -------
__global__ void k_scatter(const float* __restrict__ x, const int* __restrict__ src,
                          const int* __restrict__ dst)
{
    long idx = (long)blockIdx.x * 256 + threadIdx.x;
    if (idx >= (long)EE * DD) return;
    int e = (int)(idx >> 6), d = (int)(idx & 63);
    float a = g_logit[e] / g_sum;
    atomicAdd(&g_aggr[(long)dst[e]*DD + d], x[(long)src[e]*DD + d] * a);
}

// ---------------- fused losses: kge (blocks < KB) + nt (rest) ----------------
#define KB 512
__global__ void k_loss(const int* __restrict__ src, const int* __restrict__ dst,
                       const float* __restrict__ rel_emb,
                       const int* __restrict__ labels,
                       const float* __restrict__ w_nt, const float* __restrict__ b_nt)
{
    __shared__ float sm[256];
    if (blockIdx.x < KB) {
        float acc = 0.f;
        for (long idx = (long)blockIdx.x * 256 + threadIdx.x; idx < (long)EE * 16;
             idx += (long)KB * 256) {
            int e = (int)(idx >> 4), q = (int)(idx & 15);
            if (g_mask[e] != 0.f) {
                float4 a = *(const float4*)&g_fx[(long)src[e]*DD + q*4];
                float4 b = *(const float4*)&g_fx[(long)dst[e]*DD + q*4];
                float4 r = *(const float4*)&rel_emb[g_rel[e]*DD + q*4];
                float dx = a.x + r.x - b.x;
                float dy = a.y + r.y - b.y;
                float dz = a.z + r.z - b.z;
                float dw = a.w + r.w - b.w;
                acc += dx*dx + dy*dy + dz*dz + dw*dw;
            }
        }
        sm[threadIdx.x] = acc; __syncthreads();
        for (int s = 128; s > 0; s >>= 1) {
            if (threadIdx.x < s) sm[threadIdx.x] += sm[threadIdx.x + s];
            __syncthreads();
        }
        if (threadIdx.x == 0) atomicAdd(&g_kge, sm[0]);
    } else {
        int n = (blockIdx.x - KB) * 256 + threadIdx.x;
        float loss = 0.f;
        if (n < MM) {
            const float* xr = g_fx + (long)n * DD;
            float z0 = b_nt[0], z1 = b_nt[1], z2 = b_nt[2];
            #pragma unroll 16
            for (int k = 0; k < DD; k++) {
                float v = xr[k];
                z0 += v * w_nt[k*3 + 0];
                z1 += v * w_nt[k*3 + 1];
                z2 += v * w_nt[k*3 + 2];
            }
            float mx  = fmaxf(z0, fmaxf(z1, z2));
            float lse = mx + logf(expf(z0 - mx) + expf(z1 - mx) + expf(z2 - mx));
            int lab = labels[n];
            float zl = (lab == 0) ? z0 : ((lab == 1) ? z1 : z2);
            loss = lse - zl;
        }
        sm[threadIdx.x] = loss; __syncthreads();
        for (int s = 128; s > 0; s >>= 1) {
            if (threadIdx.x < s) sm[threadIdx.x] += sm[threadIdx.x + s];
            __syncthreads();
        }
        if (threadIdx.x == 0) atomicAdd(&g_nt, sm[0]);
    }
}

// ---------------- write loss scalars ----------------
__global__ void k_finalize(float* __restrict__ out, long off)
{
    out[off]     = g_kge / (float)((long)EE * DD);
    out[off + 1] = g_nt / (float)MM;
}

// =====================================================================================
extern "C" void kernel_launch(void* const* d_in, const int* in_sizes, int n_in,
                              void* d_out, int out_size)
{
    const int*   node_ids   = (const int*)  d_in[0];
    const int*   edge_index = (const int*)  d_in[1];
    const float* edge_attr  = (const float*)d_in[2];
    const float* tokemb     = (const float*)d_in[3];
    const int*   labels     = (const int*)  d_in[4];
    const float* kg_emb     = (const float*)d_in[5];
    const float* rel_emb    = (const float*)d_in[6];
    const float* w_e2       = (const float*)d_in[7];
    const float* b_e2       = (const float*)d_in[8];
    const float* att1_w     = (const float*)d_in[9];
    const float* att1_b     = (const float*)d_in[10];
    const float* root1      = (const float*)d_in[11];
    const float* bias1      = (const float*)d_in[12];
    const float* att2_w     = (const float*)d_in[13];
    const float* att2_b     = (const float*)d_in[14];
    const float* root2      = (const float*)d_in[15];
    const float* bias2      = (const float*)d_in[16];
    const float* w_lin1     = (const float*)d_in[17];
    const float* b_lin1     = (const float*)d_in[18];
    const float* w_lin2     = (const float*)d_in[19];
    const float* b_lin2     = (const float*)d_in[20];
    const float* w_nt       = (const float*)d_in[21];
    const float* b_nt       = (const float*)d_in[22];
    float* out = (float*)d_out;

    const int* src = edge_index;        // edge_index[0, :]
    const int* dst = edge_index + EE;   // edge_index[1, :]

    void *px_, *ph_, *pfx_, *paggr_, *pW_, *pu1_, *pu2_;
    cudaGetSymbolAddress(&px_,    g_x);
    cudaGetSymbolAddress(&ph_,    g_h);
    cudaGetSymbolAddress(&pfx_,   g_fx);
    cudaGetSymbolAddress(&paggr_, g_aggr);
    cudaGetSymbolAddress(&pu1_,   g_u1);
    cudaGetSymbolAddress(&pu2_,   g_u2);
    cudaGetSymbolAddress(&pW_,    g_W);
    float* px    = (float*)px_;
    float* ph    = (float*)ph_;
    float* pfx   = (float*)pfx_;
    float* paggr = (float*)paggr_;
    float* pu1   = (float*)pu1_;
    float* pu2   = (float*)pu2_;
    float* pW    = (float*)pW_;

    // ---- init scratch (zero aggr + tok region, gather kg nodes, reset scalars) ----
    k_init<<<(MM*16 + 255)/256, 256>>>(node_ids, kg_emb);

    // ---- tok = token_embeddings @ w_lin1 + b_lin1 (split-K over z, atomic) ----
    {
        dim3 grid(1, (TT + 127)/128, 8);
        gemm_f2<0,0,1,0><<<grid, 256>>>(tokemb, w_lin1, b_lin1, nullptr, px, TT, DD, TOKN, 96);
    }

    // ---- W[r] = relu(rel_emb @ w_e2 + b_e2) as GEMM [50,64]x[64,4096] ----
    {
        dim3 grid(4096/64, 1, 1);
        gemm_f2<1,0,0,0><<<grid, 256>>>(rel_emb, w_e2, b_e2, nullptr, pW, RR, 4096, DD, DD);
    }
    k_edgeprep<<<EB + (RR*DD + 255)/256, 256>>>(edge_attr, att1_w, att2_w);

    // ---- layer 1: x -> h (relu); gemm re-zeroes aggr for layer 2 ----
    k_p<<<(MM + 255)/256, 256>>>(px, att1_w, att1_b);
    k_logit<<<(EE + 255)/256, 256>>>(px, pu1, src, dst);
    k_expsum<<<(EE + 255)/256, 256>>>();
    k_scatter<<<(int)(((long)EE*DD + 255)/256), 256>>>(px, src, dst);
    {
        dim3 grid(1, (MM + 127)/128, 1);
        gemm_f2<1,1,0,1><<<grid, 256>>>(px, root1, bias1, paggr, ph, MM, DD, DD, DD);
    }

    // ---- layer 2: h -> final_x ----
    k_p<<<(MM + 255)/256, 256>>>(ph, att2_w, att2_b);
    k_logit<<<(EE + 255)/256, 256>>>(ph, pu2, src, dst);
    k_expsum<<<(EE + 255)/256, 256>>>();
    k_scatter<<<(int)(((long)EE*DD + 255)/256), 256>>>(ph, src, dst);
    {
        dim3 grid(1, (MM + 127)/128, 1);
        gemm_f2<0,1,0,0><<<grid, 256>>>(ph, root2, bias2, paggr, pfx, MM, DD, DD, DD);
    }

    // ---- losses (fused) ----
    k_loss<<<KB + (MM + 255)/256, 256>>>(src, dst, rel_emb, labels, w_nt, b_nt);

    // ---- final outputs: final_x @ w_lin2 + b_lin2 ----
    {
        dim3 grid(TOKN/64, (MM + 127)/128, 1);
        gemm_f2<0,0,0,0><<<grid, 256>>>(pfx, w_lin2, b_lin2, nullptr, out, MM, TOKN, DD, DD);
    }

    // ---- loss scalars at the tail of d_out ----
    k_finalize<<<1, 1>>>(out, (long)out_size - 2);
}